// round 15
// baseline (speedup 1.0000x reference)
#include <cuda_runtime.h>
#include <cuda_fp16.h>

typedef unsigned int u32;

// ---------------- problem constants ----------------
#define Tt   7
#define Ff   36
#define Uu   256
#define Bsz  32768
#define BMr  64             // batch rows per CTA (2 m-warp rows x 32)
#define NTm  512            // 16 warps = 2M x 8N
#define NCTA 512            // Bsz / BMr
#define KPAD 320            // 256 h + 36 x + 1 bias + 27 pad = 20 k16 chunks
#define NCH  20
#define KB   292            // bias row: A[.][292] = 1.0, W[292][.] = b
#define SPAD 328            // A row stride in fp16: 656B, 16B-aligned, staggered
#define ROWB (SPAD * 2)     // 656 bytes per A row
#define SWU  (NCH * 2048)   // u32 per sweep in g_Bfrag

// ---------------- smem layout ----------------
#define AH_OFF   0                         // A: 64 x 656B = 41984
#define HOLD_OFF (BMr * ROWB)              // 41984: half-0 h buffer (32KB)
#define C_OFF    (HOLD_OFF + NTm * 16 * 4) // 74752: c state (64KB)
#define SMEM_TOTAL (C_OFF + NTm * 32 * 4)  // 140288

// ---------------- device scratch (static) ----------------
// B fragments (single fp16 term) in CONSUMPTION order:
// [(s*NCH+cc)*2 + gsel]*1024 + wn*128 + lane*4 + reg
__device__ u32 g_Bfrag[4 * NCH * 2 * 1024];   // 640KB, L2-resident

// ---------------- ptx helpers ----------------
__device__ __forceinline__ u32 smem_u32(const void* p) {
    u32 a;
    asm("{ .reg .u64 t; cvta.to.shared.u64 t, %1; cvt.u32.u64 %0, t; }"
        : "=r"(a) : "l"(p));
    return a;
}
__device__ __forceinline__ float fsgm(float z) {
    float e, r;
    asm("ex2.approx.f32 %0, %1;" : "=f"(e) : "f"(-1.4426950408889634f * z));
    asm("rcp.approx.f32 %0, %1;" : "=f"(r) : "f"(1.0f + e));
    return r;
}
__device__ __forceinline__ float ftanh(float z) {
    float e, r;
    asm("ex2.approx.f32 %0, %1;" : "=f"(e) : "f"(-2.8853900817779268f * z));
    asm("rcp.approx.f32 %0, %1;" : "=f"(r) : "f"(1.0f + e));
    return fmaf(2.0f, r, -1.0f);
}
__device__ __forceinline__ void ldm4(u32* r, u32 addr) {
    asm volatile("ldmatrix.sync.aligned.m8n8.x4.shared.b16 {%0,%1,%2,%3}, [%4];"
                 : "=r"(r[0]), "=r"(r[1]), "=r"(r[2]), "=r"(r[3]) : "r"(addr));
}
__device__ __forceinline__ void mma16816(float* d, const u32* a, const u32* b) {
    asm volatile(
        "mma.sync.aligned.m16n8k16.row.col.f32.f16.f16.f32 "
        "{%0,%1,%2,%3}, {%4,%5,%6,%7}, {%8,%9}, {%0,%1,%2,%3};"
        : "+f"(d[0]), "+f"(d[1]), "+f"(d[2]), "+f"(d[3])
        : "r"(a[0]), "r"(a[1]), "r"(a[2]), "r"(a[3]), "r"(b[0]), "r"(b[1]));
}
__device__ __forceinline__ void ldg4(u32* r, const u32* p) {
    asm volatile("ld.global.nc.v4.u32 {%0,%1,%2,%3}, [%4];"
                 : "=r"(r[0]), "=r"(r[1]), "=r"(r[2]), "=r"(r[3]) : "l"(p));
}

// A store helper: fp16 at A[r][k]
__device__ __forceinline__ void a_store(char* sm, int r, int k, float v) {
    *reinterpret_cast<__half*>(sm + AH_OFF + r * ROWB + k * 2) = __float2half(v);
}

// ---------------------------------------------------------------------------
// prep: pack W = [Wr;Wk;bias@292;0] into mma B-fragment order, single fp16,
// grouped by fused sweep: s in 0..3 -> half = s>>1, pair = s&1;
// pair 0 -> gates (i=0, g=2); pair 1 -> gates (f=1, o=3).
// ---------------------------------------------------------------------------
__global__ void prep_kernel(const float* __restrict__ Wr,
                            const float* __restrict__ Wk,
                            const float* __restrict__ bia) {
    int idx = blockIdx.x * 512 + threadIdx.x;
    if (idx >= 4 * NCH * 2 * 1024) return;
    int reg  = idx & 3;
    int lane = (idx >> 2) & 31;
    int wn   = (idx >> 7) & 7;
    int rest = idx >> 10;
    int gsel = rest & 1;
    int bc   = rest >> 1;
    int cc   = bc % NCH;
    int s    = bc / NCH;           // 0..3

    int half = s >> 1;
    int pair = s & 1;
    int gate = (pair == 0) ? (gsel ? 2 : 0) : (gsel ? 3 : 1);

    int n_local = wn * 16 + (reg >> 1) * 8 + (lane >> 2);
    int ncol    = gate * 256 + half * 128 + n_local;
    int k0      = cc * 16 + (reg & 1) * 8 + ((lane & 3) << 1);

    float v0 = 0.f, v1 = 0.f;
    if (k0 < 256)       v0 = Wr[(size_t)k0 * 1024 + ncol];
    else if (k0 < KB)   v0 = Wk[(size_t)(k0 - 256) * 1024 + ncol];
    else if (k0 == KB)  v0 = bia[ncol];
    int k1 = k0 + 1;
    if (k1 < 256)       v1 = Wr[(size_t)k1 * 1024 + ncol];
    else if (k1 < KB)   v1 = Wk[(size_t)(k1 - 256) * 1024 + ncol];
    else if (k1 == KB)  v1 = bia[ncol];

    unsigned short e0 = __half_as_ushort(__float2half(v0));
    unsigned short e1 = __half_as_ushort(__float2half(v1));
    g_Bfrag[idx] = ((u32)e1 << 16) | (u32)e0;
}

// chunk-worth of HMMAs consuming buffer pf (8 u32: gsel0 regs0-3, gsel1 regs0-3)
#define DO_CHUNK(cc, pf)                                                    \
    do {                                                                    \
        const u32 ao = aBase + (u32)(cc) * 32;                              \
        u32 a0[4], a1[4];                                                   \
        ldm4(a0, ao);                                                       \
        ldm4(a1, ao + 16 * ROWB);                                           \
        _Pragma("unroll")                                                   \
        for (int g = 0; g < 2; g++)                                         \
            _Pragma("unroll")                                               \
            for (int nt = 0; nt < 2; nt++) {                                \
                mma16816(acc[g][0][nt], a0, &(pf)[g * 4 + nt * 2]);         \
                mma16816(acc[g][1][nt], a1, &(pf)[g * 4 + nt * 2]);         \
            }                                                               \
    } while (0)

#define LOADB(pf, p)                                                        \
    do {                                                                    \
        ldg4(&(pf)[0], (p));                                                \
        ldg4(&(pf)[4], (p) + 1024);                                         \
    } while (0)

// ---------------------------------------------------------------------------
// main LSTM kernel: fused gate pairs, fp16 1-term, static double-buffered B,
// bias folded into GEMM, c in smem.
// ---------------------------------------------------------------------------
__global__ void __launch_bounds__(NTm, 1)
lstm_hmma(const float* __restrict__ x,    // [B,T,F]
          const float* __restrict__ h0,   // [B,U]
          const float* __restrict__ c0,   // [B,U]
          float* __restrict__ out)        // [B,T,U]
{
    extern __shared__ char sm[];
    const u32 smb  = smem_u32(sm);
    const int tid  = threadIdx.x;
    const int lane = tid & 31;
    const int wid  = tid >> 5;
    const int wm   = wid >> 3;       // 0..1  (M warp row)
    const int wn   = wid & 7;        // 0..7  (N warp col)
    const int cta  = blockIdx.x;
    const int row0 = cta * BMr;
    float* holdSm = reinterpret_cast<float*>(sm + HOLD_OFF) + tid * 16;
    float* cSm    = reinterpret_cast<float*>(sm + C_OFF);

    // ---- init A: h0 (fp16), x(t=0), bias-one col, zero pad ----
    for (int i = tid; i < BMr * Uu; i += NTm) {
        int r = i >> 8, k = i & 255;
        a_store(sm, r, k, h0[(size_t)(row0 + r) * Uu + k]);
    }
    for (int i = tid; i < BMr * Ff; i += NTm) {
        int r = i / Ff, f = i - r * Ff;
        a_store(sm, r, 256 + f, x[(size_t)(row0 + r) * (Tt * Ff) + f]);
    }
    for (int i = tid; i < BMr * (KPAD - KB); i += NTm) {
        int r = i / (KPAD - KB), k = KB + (i - r * (KPAD - KB));
        a_store(sm, r, k, (k == KB) ? 1.0f : 0.0f);
    }

    // ---- init c state in smem (this thread's 32 lattice points) ----
#pragma unroll
    for (int j = 0; j < 32; j++) {
        const int half = j >> 4, jj = j & 15;
        const int mt = jj >> 3, nt = (jj >> 2) & 1, e = jj & 3;
        const int ucol = half * 128 + wn * 16 + nt * 8 + 2 * (lane & 3) + (e & 1);
        const int row  = wm * 32 + mt * 16 + (lane >> 2) + ((e >> 1) << 3);
        cSm[j * NTm + tid] = c0[(size_t)(row0 + row) * Uu + ucol];
    }
    __syncthreads();

    // ldmatrix per-lane base address (m-tile 0)
    const u32 aBase = smb + AH_OFF
                    + (u32)(wm * 32 + (lane & 15)) * ROWB
                    + (u32)((lane >> 4) * 16);

    // ---- B double-buffer with static addressing ----
    const u32* bFrag = g_Bfrag + (wn * 128 + lane * 4);
    u32 pfA[8], pfB[8];
    LOADB(pfA, bFrag);          // sweep 0, chunk 0
    LOADB(pfB, bFrag + 2048);   // sweep 0, chunk 1

    float gv[16];

#pragma unroll 1
    for (int t = 0; t < Tt; t++) {
#pragma unroll
        for (int s = 0; s < 4; s++) {
            const int half = s >> 1;
            const int pair = s & 1;
            const u32* bS = bFrag + s * SWU;
            const u32* bN = bFrag + ((s + 1) & 3) * SWU;

            float acc[2][2][2][4];   // [gate][mt][nt][e]
#pragma unroll
            for (int g = 0; g < 2; g++)
#pragma unroll
                for (int a = 0; a < 2; a++)
#pragma unroll
                    for (int b = 0; b < 2; b++)
#pragma unroll
                        for (int e = 0; e < 4; e++) acc[g][a][b][e] = 0.f;

            // ---- mainloop: 20 chunks, fully static, no barriers ----
#pragma unroll
            for (int cc = 0; cc < NCH; cc += 2) {
                DO_CHUNK(cc, pfA);
                LOADB(pfA, (cc + 2 < NCH) ? bS + (cc + 2) * 2048 : bN);
                DO_CHUNK(cc + 1, pfB);
                LOADB(pfB, (cc + 3 < NCH) ? bS + (cc + 3) * 2048 : bN + 2048);
            }

            // ---- fused epilogue (bias already inside acc) ----
#pragma unroll
            for (int j = 0; j < 16; j++) {
                const int mt = j >> 3, nt = (j >> 2) & 1, e = j & 3;
                const float z0 = acc[0][mt][nt][e];
                const float z1 = acc[1][mt][nt][e];
                if (pair == 0) {
                    gv[j] = fsgm(z0) * ftanh(z1);      // sigma(i)*tanh(g)
                } else {
                    float* cp = &cSm[(half * 16 + j) * NTm + tid];
                    const float cn = fsgm(z0) * (*cp) + gv[j];
                    *cp = cn;
                    gv[j] = fsgm(z1) * ftanh(cn);      // h = sigma(o)*tanh(c)
                }
            }

            if (pair == 1) {
                // write h to out (float2 pairs share a row)
#pragma unroll
                for (int jp = 0; jp < 8; jp++) {
                    const int j  = 2 * jp;
                    const int mt = j >> 3, nt = (j >> 2) & 1, e = j & 3;
                    const int ucol = half * 128 + wn * 16 + nt * 8 + 2 * (lane & 3);
                    const int row  = wm * 32 + mt * 16 + (lane >> 2) + ((e >> 1) << 3);
                    *reinterpret_cast<float2*>(
                        out + ((size_t)(row0 + row) * Tt + t) * Uu + ucol) =
                        make_float2(gv[j], gv[j + 1]);
                }
                if (half == 0) {   // stash half-0 h in smem until step end
#pragma unroll
                    for (int q = 0; q < 4; q++)
                        *reinterpret_cast<float4*>(holdSm + 4 * q) =
                            make_float4(gv[4 * q], gv[4 * q + 1],
                                        gv[4 * q + 2], gv[4 * q + 3]);
                }
            }
        } // sweeps

        // ---- step boundary: write h (both halves) back into A, load x(t+1) ----
        __syncthreads();   // all A reads of this step complete
#pragma unroll
        for (int j = 0; j < 16; j++) {
            const int mt = j >> 3, nt = (j >> 2) & 1, e = j & 3;
            const int loc = wn * 16 + nt * 8 + 2 * (lane & 3) + (e & 1);
            const int row = wm * 32 + mt * 16 + (lane >> 2) + ((e >> 1) << 3);
            a_store(sm, row, 128 + loc, gv[j]);        // half 1 (in regs)
            a_store(sm, row, loc,       holdSm[j]);    // half 0 (from smem)
        }
        if (t + 1 < Tt) {
            for (int i = tid; i < BMr * Ff; i += NTm) {
                int r = i / Ff, f = i - r * Ff;
                a_store(sm, r, 256 + f,
                        x[((size_t)(row0 + r) * Tt + (t + 1)) * Ff + f]);
            }
        }
        __syncthreads();
    } // t
}

// ---------------------------------------------------------------------------
// Harness entry point
// ---------------------------------------------------------------------------
extern "C" void kernel_launch(void* const* d_in, const int* in_sizes, int n_in,
                              void* d_out, int out_size) {
    const float* x  = (const float*)d_in[0];  // [B,T,F]
    const float* h0 = (const float*)d_in[1];  // [B,U]
    const float* c0 = (const float*)d_in[2];  // [B,U]
    const float* Wk = (const float*)d_in[3];  // [F,4U]
    const float* Wr = (const float*)d_in[4];  // [U,4U]
    const float* b  = (const float*)d_in[5];  // [4U]
    float* out = (float*)d_out;               // [B,T,U]

    prep_kernel<<<(4 * NCH * 2 * 1024 + 511) / 512, 512>>>(Wr, Wk, b);

    cudaFuncSetAttribute(lstm_hmma,
                         cudaFuncAttributeMaxDynamicSharedMemorySize, SMEM_TOTAL);
    lstm_hmma<<<NCTA, NTm, SMEM_TOTAL>>>(x, h0, c0, out);
}

// round 16
// speedup vs baseline: 1.9493x; 1.9493x over previous
#include <cuda_runtime.h>
#include <cuda_fp16.h>

typedef unsigned int u32;

// ---------------- problem constants ----------------
#define Tt   7
#define Ff   36
#define Uu   256
#define Bsz  32768
#define BMr  64             // batch rows per CTA (2 m-warp rows x 32)
#define NTm  512            // 16 warps = 2M x 8N
#define NCTA 512            // Bsz / BMr
#define KPAD 320            // 256 h + 36 x + 1 bias + 27 pad = 20 k16 chunks
#define NCH  20
#define KB   292            // bias row: A[.][292] = 1.0, W[292][.] = b
#define SPAD 328            // A row stride in fp16: 656B, 16B-aligned, staggered
#define ROWB (SPAD * 2)     // 656 bytes per A row
#define CPS  (4 * NCH)      // 80 chunks per step

// ---------------- smem layout ----------------
#define AH_OFF   0                         // A: 64 x 656B = 41984
#define HOLD_OFF (BMr * ROWB)              // 41984: half-0 h buffer (32KB)
#define C_OFF    (HOLD_OFF + NTm * 16 * 4) // 74752: c state (64KB)
#define SMEM_TOTAL (C_OFF + NTm * 32 * 4)  // 140288

// ---------------- device scratch (static) ----------------
// B fragments (single fp16 term) in CONSUMPTION order:
// [(s*NCH+cc)*2 + gsel]*1024 + wn*128 + lane*4 + reg
__device__ u32 g_Bfrag[4 * NCH * 2 * 1024];   // 640KB, L2-resident

// ---------------- ptx helpers ----------------
__device__ __forceinline__ u32 smem_u32(const void* p) {
    u32 a;
    asm("{ .reg .u64 t; cvta.to.shared.u64 t, %1; cvt.u32.u64 %0, t; }"
        : "=r"(a) : "l"(p));
    return a;
}
__device__ __forceinline__ float fsgm(float z) {
    float e, r;
    asm("ex2.approx.f32 %0, %1;" : "=f"(e) : "f"(-1.4426950408889634f * z));
    asm("rcp.approx.f32 %0, %1;" : "=f"(r) : "f"(1.0f + e));
    return r;
}
__device__ __forceinline__ float ftanh(float z) {
    float e, r;
    asm("ex2.approx.f32 %0, %1;" : "=f"(e) : "f"(-2.8853900817779268f * z));
    asm("rcp.approx.f32 %0, %1;" : "=f"(r) : "f"(1.0f + e));
    return fmaf(2.0f, r, -1.0f);
}
__device__ __forceinline__ void ldm4(u32* r, u32 addr) {
    asm volatile("ldmatrix.sync.aligned.m8n8.x4.shared.b16 {%0,%1,%2,%3}, [%4];"
                 : "=r"(r[0]), "=r"(r[1]), "=r"(r[2]), "=r"(r[3]) : "r"(addr));
}
__device__ __forceinline__ void mma16816(float* d, const u32* a, const u32* b) {
    asm volatile(
        "mma.sync.aligned.m16n8k16.row.col.f32.f16.f16.f32 "
        "{%0,%1,%2,%3}, {%4,%5,%6,%7}, {%8,%9}, {%0,%1,%2,%3};"
        : "+f"(d[0]), "+f"(d[1]), "+f"(d[2]), "+f"(d[3])
        : "r"(a[0]), "r"(a[1]), "r"(a[2]), "r"(a[3]), "r"(b[0]), "r"(b[1]));
}
__device__ __forceinline__ void ldg4(u32* r, const u32* p) {
    asm volatile("ld.global.nc.v4.u32 {%0,%1,%2,%3}, [%4];"
                 : "=r"(r[0]), "=r"(r[1]), "=r"(r[2]), "=r"(r[3]) : "l"(p));
}

// A store helper: fp16 at A[r][k]
__device__ __forceinline__ void a_store(char* sm, int r, int k, float v) {
    *reinterpret_cast<__half*>(sm + AH_OFF + r * ROWB + k * 2) = __float2half(v);
}

// ---------------------------------------------------------------------------
// prep: pack W = [Wr;Wk;bias@292;0] into mma B-fragment order, single fp16,
// grouped by fused sweep: s in 0..3 -> half = s>>1, pair = s&1;
// pair 0 -> gates (i=0, g=2); pair 1 -> gates (f=1, o=3).
// ---------------------------------------------------------------------------
__global__ void prep_kernel(const float* __restrict__ Wr,
                            const float* __restrict__ Wk,
                            const float* __restrict__ bia) {
    int idx = blockIdx.x * 512 + threadIdx.x;
    if (idx >= 4 * NCH * 2 * 1024) return;
    int reg  = idx & 3;
    int lane = (idx >> 2) & 31;
    int wn   = (idx >> 7) & 7;
    int rest = idx >> 10;
    int gsel = rest & 1;
    int bc   = rest >> 1;
    int cc   = bc % NCH;
    int s    = bc / NCH;           // 0..3

    int half = s >> 1;
    int pair = s & 1;
    int gate = (pair == 0) ? (gsel ? 2 : 0) : (gsel ? 3 : 1);

    int n_local = wn * 16 + (reg >> 1) * 8 + (lane >> 2);
    int ncol    = gate * 256 + half * 128 + n_local;
    int k0      = cc * 16 + (reg & 1) * 8 + ((lane & 3) << 1);

    float v0 = 0.f, v1 = 0.f;
    if (k0 < 256)       v0 = Wr[(size_t)k0 * 1024 + ncol];
    else if (k0 < KB)   v0 = Wk[(size_t)(k0 - 256) * 1024 + ncol];
    else if (k0 == KB)  v0 = bia[ncol];
    int k1 = k0 + 1;
    if (k1 < 256)       v1 = Wr[(size_t)k1 * 1024 + ncol];
    else if (k1 < KB)   v1 = Wk[(size_t)(k1 - 256) * 1024 + ncol];
    else if (k1 == KB)  v1 = bia[ncol];

    unsigned short e0 = __half_as_ushort(__float2half(v0));
    unsigned short e1 = __half_as_ushort(__float2half(v1));
    g_Bfrag[idx] = ((u32)e1 << 16) | (u32)e0;
}

// chunk-worth of HMMAs consuming buffer pf (8 u32: gsel0 regs0-3, gsel1 regs0-3)
#define DO_CHUNK(cc, pf)                                                    \
    do {                                                                    \
        const u32 ao = aBase + (u32)(cc) * 32;                              \
        u32 a0[4], a1[4];                                                   \
        ldm4(a0, ao);                                                       \
        ldm4(a1, ao + 16 * ROWB);                                           \
        _Pragma("unroll")                                                   \
        for (int g = 0; g < 2; g++)                                         \
            _Pragma("unroll")                                               \
            for (int nt = 0; nt < 2; nt++) {                                \
                mma16816(acc[g][0][nt], a0, &(pf)[g * 4 + nt * 2]);         \
                mma16816(acc[g][1][nt], a1, &(pf)[g * 4 + nt * 2]);         \
            }                                                               \
    } while (0)

#define PREFETCH(pf)                                                        \
    do {                                                                    \
        const u32* _p = bBase + (size_t)pi * 2048;                          \
        ldg4(&(pf)[0], _p);                                                 \
        ldg4(&(pf)[4], _p + 1024);                                          \
        if (++pi == CPS) pi = 0;                                            \
    } while (0)

// ---------------------------------------------------------------------------
// main LSTM kernel: fused gate pairs, fp16 1-term, double-buffered B,
// bias folded into GEMM, c in smem. (R14 loop structure — no static unroll.)
// ---------------------------------------------------------------------------
__global__ void __launch_bounds__(NTm, 1)
lstm_hmma(const float* __restrict__ x,    // [B,T,F]
          const float* __restrict__ h0,   // [B,U]
          const float* __restrict__ c0,   // [B,U]
          float* __restrict__ out)        // [B,T,U]
{
    extern __shared__ char sm[];
    const u32 smb  = smem_u32(sm);
    const int tid  = threadIdx.x;
    const int lane = tid & 31;
    const int wid  = tid >> 5;
    const int wm   = wid >> 3;       // 0..1  (M warp row)
    const int wn   = wid & 7;        // 0..7  (N warp col)
    const int cta  = blockIdx.x;
    const int row0 = cta * BMr;
    float* holdSm = reinterpret_cast<float*>(sm + HOLD_OFF) + tid * 16;
    float* cSm    = reinterpret_cast<float*>(sm + C_OFF);

    // ---- init A: h0 (fp16), x(t=0), bias-one col, zero pad ----
    for (int i = tid; i < BMr * Uu; i += NTm) {
        int r = i >> 8, k = i & 255;
        a_store(sm, r, k, h0[(size_t)(row0 + r) * Uu + k]);
    }
    for (int i = tid; i < BMr * Ff; i += NTm) {
        int r = i / Ff, f = i - r * Ff;
        a_store(sm, r, 256 + f, x[(size_t)(row0 + r) * (Tt * Ff) + f]);
    }
    for (int i = tid; i < BMr * (KPAD - KB); i += NTm) {
        int r = i / (KPAD - KB), k = KB + (i - r * (KPAD - KB));
        a_store(sm, r, k, (k == KB) ? 1.0f : 0.0f);
    }

    // ---- init c state in smem (this thread's 32 lattice points) ----
#pragma unroll
    for (int j = 0; j < 32; j++) {
        const int half = j >> 4, jj = j & 15;
        const int mt = jj >> 3, nt = (jj >> 2) & 1, e = jj & 3;
        const int ucol = half * 128 + wn * 16 + nt * 8 + 2 * (lane & 3) + (e & 1);
        const int row  = wm * 32 + mt * 16 + (lane >> 2) + ((e >> 1) << 3);
        cSm[j * NTm + tid] = c0[(size_t)(row0 + row) * Uu + ucol];
    }
    __syncthreads();

    // ldmatrix per-lane base address (m-tile 0)
    const u32 aBase = smb + AH_OFF
                    + (u32)(wm * 32 + (lane & 15)) * ROWB
                    + (u32)((lane >> 4) * 16);

    // ---- B double-buffer: pfA = even chunks, pfB = odd chunks ----
    const u32* bBase = g_Bfrag + (wn * 128 + lane * 4);
    int pi = 0;
    u32 pfA[8], pfB[8];
    PREFETCH(pfA);     // chunk 0
    PREFETCH(pfB);     // chunk 1

    float gv[16];

#pragma unroll 1
    for (int t = 0; t < Tt; t++) {
#pragma unroll 1
        for (int s = 0; s < 4; s++) {
            const int half = s >> 1;
            const int pair = s & 1;

            float acc[2][2][2][4];   // [gate][mt][nt][e]
#pragma unroll
            for (int g = 0; g < 2; g++)
#pragma unroll
                for (int a = 0; a < 2; a++)
#pragma unroll
                    for (int b = 0; b < 2; b++)
#pragma unroll
                        for (int e = 0; e < 4; e++) acc[g][a][b][e] = 0.f;

            // ---- mainloop: 20 chunks, double-buffered, no barriers ----
#pragma unroll 1
            for (int cc = 0; cc < NCH; cc += 2) {
                DO_CHUNK(cc, pfA);
                PREFETCH(pfA);           // refill: 2 chunks ahead
                DO_CHUNK(cc + 1, pfB);
                PREFETCH(pfB);
            }

            // ---- fused epilogue (bias already inside acc) ----
#pragma unroll
            for (int j = 0; j < 16; j++) {
                const int mt = j >> 3, nt = (j >> 2) & 1, e = j & 3;
                const float z0 = acc[0][mt][nt][e];
                const float z1 = acc[1][mt][nt][e];
                if (pair == 0) {
                    gv[j] = fsgm(z0) * ftanh(z1);      // sigma(i)*tanh(g)
                } else {
                    float* cp = &cSm[(half * 16 + j) * NTm + tid];
                    const float cn = fsgm(z0) * (*cp) + gv[j];
                    *cp = cn;
                    gv[j] = fsgm(z1) * ftanh(cn);      // h = sigma(o)*tanh(c)
                }
            }

            if (pair == 1) {
                // write h to out (float2 pairs share a row)
#pragma unroll
                for (int jp = 0; jp < 8; jp++) {
                    const int j  = 2 * jp;
                    const int mt = j >> 3, nt = (j >> 2) & 1, e = j & 3;
                    const int ucol = half * 128 + wn * 16 + nt * 8 + 2 * (lane & 3);
                    const int row  = wm * 32 + mt * 16 + (lane >> 2) + ((e >> 1) << 3);
                    *reinterpret_cast<float2*>(
                        out + ((size_t)(row0 + row) * Tt + t) * Uu + ucol) =
                        make_float2(gv[j], gv[j + 1]);
                }
                if (half == 0) {   // stash half-0 h in smem until step end
#pragma unroll
                    for (int q = 0; q < 4; q++)
                        *reinterpret_cast<float4*>(holdSm + 4 * q) =
                            make_float4(gv[4 * q], gv[4 * q + 1],
                                        gv[4 * q + 2], gv[4 * q + 3]);
                }
            }
        } // sweeps

        // ---- step boundary: write h (both halves) back into A, load x(t+1) ----
        __syncthreads();   // all A reads of this step complete
#pragma unroll
        for (int j = 0; j < 16; j++) {
            const int mt = j >> 3, nt = (j >> 2) & 1, e = j & 3;
            const int loc = wn * 16 + nt * 8 + 2 * (lane & 3) + (e & 1);
            const int row = wm * 32 + mt * 16 + (lane >> 2) + ((e >> 1) << 3);
            a_store(sm, row, 128 + loc, gv[j]);        // half 1 (in regs)
            a_store(sm, row, loc,       holdSm[j]);    // half 0 (from smem)
        }
        if (t + 1 < Tt) {
            for (int i = tid; i < BMr * Ff; i += NTm) {
                int r = i / Ff, f = i - r * Ff;
                a_store(sm, r, 256 + f,
                        x[((size_t)(row0 + r) * Tt + (t + 1)) * Ff + f]);
            }
        }
        __syncthreads();
    } // t
}

// ---------------------------------------------------------------------------
// Harness entry point
// ---------------------------------------------------------------------------
extern "C" void kernel_launch(void* const* d_in, const int* in_sizes, int n_in,
                              void* d_out, int out_size) {
    const float* x  = (const float*)d_in[0];  // [B,T,F]
    const float* h0 = (const float*)d_in[1];  // [B,U]
    const float* c0 = (const float*)d_in[2];  // [B,U]
    const float* Wk = (const float*)d_in[3];  // [F,4U]
    const float* Wr = (const float*)d_in[4];  // [U,4U]
    const float* b  = (const float*)d_in[5];  // [4U]
    float* out = (float*)d_out;               // [B,T,U]

    prep_kernel<<<(4 * NCH * 2 * 1024 + 511) / 512, 512>>>(Wr, Wk, b);

    cudaFuncSetAttribute(lstm_hmma,
                         cudaFuncAttributeMaxDynamicSharedMemorySize, SMEM_TOTAL);
    lstm_hmma<<<NCTA, NTm, SMEM_TOTAL>>>(x, h0, c0, out);
}

// round 17
// speedup vs baseline: 2.3476x; 1.2043x over previous
#include <cuda_runtime.h>
#include <cuda_fp16.h>

typedef unsigned int u32;

// ---------------- problem constants ----------------
#define Tt   7
#define Ff   36
#define Uu   256
#define Bsz  32768
#define BMr  32             // batch rows per CTA (2 m-tiles of 16)
#define NTm  512            // 16 warps, each = one wn slice of full N=256
#define NCTA 1024           // Bsz / BMr -> 6.92 waves on 148 SMs
#define KPAD 320            // 256 h + 36 x + 1 bias + 27 pad = 20 k16 chunks
#define NCH  20
#define KB   292            // bias row: A[.][292] = 1.0, W[292][.] = b
#define SPAD 328            // A row stride in fp16: 656B, 16B-aligned, staggered
#define ROWB (SPAD * 2)     // 656 bytes per A row
#define CPS  (2 * NCH)      // 40 chunks per step (2 full-width sweeps x 20)

// ---------------- smem layout ----------------
#define AH_OFF   0                         // A: 32 x 656B = 20992
#define C_OFF    (BMr * ROWB)              // 20992: c state (32KB)
#define SMEM_TOTAL (C_OFF + NTm * 16 * 4)  // 53760

// ---------------- device scratch (static) ----------------
// B fragments (single fp16) in CONSUMPTION order:
// [(s*NCH+cc)*2 + gsel]*2048 + wn*128 + lane*4 + reg
// s=0 -> gates (i=0, g=2); s=1 -> gates (f=1, o=3); full N=256 per block.
__device__ u32 g_Bfrag[2 * NCH * 2 * 2048];   // 640KB, L2-resident

// ---------------- ptx helpers ----------------
__device__ __forceinline__ u32 smem_u32(const void* p) {
    u32 a;
    asm("{ .reg .u64 t; cvta.to.shared.u64 t, %1; cvt.u32.u64 %0, t; }"
        : "=r"(a) : "l"(p));
    return a;
}
__device__ __forceinline__ float fsgm(float z) {
    float e, r;
    asm("ex2.approx.f32 %0, %1;" : "=f"(e) : "f"(-1.4426950408889634f * z));
    asm("rcp.approx.f32 %0, %1;" : "=f"(r) : "f"(1.0f + e));
    return r;
}
__device__ __forceinline__ float ftanh(float z) {
    float e, r;
    asm("ex2.approx.f32 %0, %1;" : "=f"(e) : "f"(-2.8853900817779268f * z));
    asm("rcp.approx.f32 %0, %1;" : "=f"(r) : "f"(1.0f + e));
    return fmaf(2.0f, r, -1.0f);
}
__device__ __forceinline__ void ldm4(u32* r, u32 addr) {
    asm volatile("ldmatrix.sync.aligned.m8n8.x4.shared.b16 {%0,%1,%2,%3}, [%4];"
                 : "=r"(r[0]), "=r"(r[1]), "=r"(r[2]), "=r"(r[3]) : "r"(addr));
}
__device__ __forceinline__ void mma16816(float* d, const u32* a, const u32* b) {
    asm volatile(
        "mma.sync.aligned.m16n8k16.row.col.f32.f16.f16.f32 "
        "{%0,%1,%2,%3}, {%4,%5,%6,%7}, {%8,%9}, {%0,%1,%2,%3};"
        : "+f"(d[0]), "+f"(d[1]), "+f"(d[2]), "+f"(d[3])
        : "r"(a[0]), "r"(a[1]), "r"(a[2]), "r"(a[3]), "r"(b[0]), "r"(b[1]));
}
__device__ __forceinline__ void ldg4(u32* r, const u32* p) {
    asm volatile("ld.global.nc.v4.u32 {%0,%1,%2,%3}, [%4];"
                 : "=r"(r[0]), "=r"(r[1]), "=r"(r[2]), "=r"(r[3]) : "l"(p));
}

// A store helper: fp16 at A[r][k]
__device__ __forceinline__ void a_store(char* sm, int r, int k, float v) {
    *reinterpret_cast<__half*>(sm + AH_OFF + r * ROWB + k * 2) = __float2half(v);
}

// ---------------------------------------------------------------------------
// prep: pack W = [Wr;Wk;bias@292;0] into mma B-fragment order, single fp16,
// grouped by full-width sweep: s=0 -> (i,g), s=1 -> (f,o); wn covers 16 slices.
// ---------------------------------------------------------------------------
__global__ void prep_kernel(const float* __restrict__ Wr,
                            const float* __restrict__ Wk,
                            const float* __restrict__ bia) {
    int idx = blockIdx.x * 512 + threadIdx.x;
    if (idx >= 2 * NCH * 2 * 2048) return;
    int reg  = idx & 3;
    int lane = (idx >> 2) & 31;
    int wn   = (idx >> 7) & 15;
    int rest = idx >> 11;
    int gsel = rest & 1;
    int bc   = rest >> 1;
    int cc   = bc % NCH;
    int s    = bc / NCH;           // 0..1

    int gate = (s == 0) ? (gsel ? 2 : 0) : (gsel ? 3 : 1);

    int n_local = wn * 16 + (reg >> 1) * 8 + (lane >> 2);   // 0..255
    int ncol    = gate * 256 + n_local;
    int k0      = cc * 16 + (reg & 1) * 8 + ((lane & 3) << 1);

    float v0 = 0.f, v1 = 0.f;
    if (k0 < 256)       v0 = Wr[(size_t)k0 * 1024 + ncol];
    else if (k0 < KB)   v0 = Wk[(size_t)(k0 - 256) * 1024 + ncol];
    else if (k0 == KB)  v0 = bia[ncol];
    int k1 = k0 + 1;
    if (k1 < 256)       v1 = Wr[(size_t)k1 * 1024 + ncol];
    else if (k1 < KB)   v1 = Wk[(size_t)(k1 - 256) * 1024 + ncol];
    else if (k1 == KB)  v1 = bia[ncol];

    unsigned short e0 = __half_as_ushort(__float2half(v0));
    unsigned short e1 = __half_as_ushort(__float2half(v1));
    g_Bfrag[idx] = ((u32)e1 << 16) | (u32)e0;
}

// chunk-worth of HMMAs consuming buffer pf (8 u32: gsel0 regs0-3, gsel1 regs0-3)
#define DO_CHUNK(cc, pf)                                                    \
    do {                                                                    \
        const u32 ao = aBase + (u32)(cc) * 32;                              \
        u32 a0[4], a1[4];                                                   \
        ldm4(a0, ao);                                                       \
        ldm4(a1, ao + 16 * ROWB);                                           \
        _Pragma("unroll")                                                   \
        for (int g = 0; g < 2; g++)                                         \
            _Pragma("unroll")                                               \
            for (int nt = 0; nt < 2; nt++) {                                \
                mma16816(acc[g][0][nt], a0, &(pf)[g * 4 + nt * 2]);         \
                mma16816(acc[g][1][nt], a1, &(pf)[g * 4 + nt * 2]);         \
            }                                                               \
    } while (0)

#define PREFETCH(pf)                                                        \
    do {                                                                    \
        const u32* _p = bBase + (size_t)pi * 4096;                          \
        ldg4(&(pf)[0], _p);                                                 \
        ldg4(&(pf)[4], _p + 2048);                                          \
        if (++pi == CPS) pi = 0;                                            \
    } while (0)

// ---------------------------------------------------------------------------
// main LSTM kernel: 1024 CTAs x 512 threads; 2 full-width fused sweeps per
// step; fp16 1-term; bias folded into GEMM; c in smem; double-buffered B.
// ---------------------------------------------------------------------------
__global__ void __launch_bounds__(NTm, 1)
lstm_hmma(const float* __restrict__ x,    // [B,T,F]
          const float* __restrict__ h0,   // [B,U]
          const float* __restrict__ c0,   // [B,U]
          float* __restrict__ out)        // [B,T,U]
{
    extern __shared__ char sm[];
    const u32 smb  = smem_u32(sm);
    const int tid  = threadIdx.x;
    const int lane = tid & 31;
    const int wn   = tid >> 5;       // 0..15 (N warp slice: cols wn*16..+15)
    const int cta  = blockIdx.x;
    const int row0 = cta * BMr;
    float* cSm = reinterpret_cast<float*>(sm + C_OFF);

    // ---- init A: h0 (fp16), x(t=0), bias-one col, zero pad ----
    for (int i = tid; i < BMr * Uu; i += NTm) {
        int r = i >> 8, k = i & 255;
        a_store(sm, r, k, h0[(size_t)(row0 + r) * Uu + k]);
    }
    for (int i = tid; i < BMr * Ff; i += NTm) {
        int r = i / Ff, f = i - r * Ff;
        a_store(sm, r, 256 + f, x[(size_t)(row0 + r) * (Tt * Ff) + f]);
    }
    for (int i = tid; i < BMr * (KPAD - KB); i += NTm) {
        int r = i / (KPAD - KB), k = KB + (i - r * (KPAD - KB));
        a_store(sm, r, k, (k == KB) ? 1.0f : 0.0f);
    }

    // ---- init c state in smem (this thread's 16 lattice points) ----
#pragma unroll
    for (int j = 0; j < 16; j++) {
        const int mt = j >> 3, nt = (j >> 2) & 1, e = j & 3;
        const int ucol = wn * 16 + nt * 8 + 2 * (lane & 3) + (e & 1);
        const int row  = mt * 16 + (lane >> 2) + ((e >> 1) << 3);
        cSm[j * NTm + tid] = c0[(size_t)(row0 + row) * Uu + ucol];
    }
    __syncthreads();

    // ldmatrix per-lane base address (m-tile 0)
    const u32 aBase = smb + AH_OFF
                    + (u32)(lane & 15) * ROWB
                    + (u32)((lane >> 4) * 16);

    // ---- B double-buffer: pfA = even chunks, pfB = odd chunks ----
    const u32* bBase = g_Bfrag + (wn * 128 + lane * 4);
    int pi = 0;
    u32 pfA[8], pfB[8];
    PREFETCH(pfA);     // chunk 0
    PREFETCH(pfB);     // chunk 1

    float gv[16];

#pragma unroll 1
    for (int t = 0; t < Tt; t++) {
#pragma unroll 1
        for (int s = 0; s < 2; s++) {      // s=0: (i,g)  s=1: (f,o)
            float acc[2][2][2][4];         // [gate][mt][nt][e]
#pragma unroll
            for (int g = 0; g < 2; g++)
#pragma unroll
                for (int a = 0; a < 2; a++)
#pragma unroll
                    for (int b = 0; b < 2; b++)
#pragma unroll
                        for (int e = 0; e < 4; e++) acc[g][a][b][e] = 0.f;

            // ---- mainloop: 20 chunks, double-buffered, no barriers ----
#pragma unroll 1
            for (int cc = 0; cc < NCH; cc += 2) {
                DO_CHUNK(cc, pfA);
                PREFETCH(pfA);           // refill: 2 chunks ahead
                DO_CHUNK(cc + 1, pfB);
                PREFETCH(pfB);
            }

            // ---- fused epilogue (bias already inside acc) ----
            if (s == 0) {
#pragma unroll
                for (int j = 0; j < 16; j++) {
                    const int mt = j >> 3, nt = (j >> 2) & 1, e = j & 3;
                    gv[j] = fsgm(acc[0][mt][nt][e]) * ftanh(acc[1][mt][nt][e]);
                }
            } else {
#pragma unroll
                for (int j = 0; j < 16; j++) {
                    const int mt = j >> 3, nt = (j >> 2) & 1, e = j & 3;
                    float* cp = &cSm[j * NTm + tid];
                    const float cn = fsgm(acc[0][mt][nt][e]) * (*cp) + gv[j];
                    *cp = cn;
                    gv[j] = fsgm(acc[1][mt][nt][e]) * ftanh(cn);  // h
                }
                // write h to out (float2 pairs share a row)
#pragma unroll
                for (int jp = 0; jp < 8; jp++) {
                    const int j  = 2 * jp;
                    const int mt = j >> 3, nt = (j >> 2) & 1, e = j & 3;
                    const int ucol = wn * 16 + nt * 8 + 2 * (lane & 3);
                    const int row  = mt * 16 + (lane >> 2) + ((e >> 1) << 3);
                    *reinterpret_cast<float2*>(
                        out + ((size_t)(row0 + row) * Tt + t) * Uu + ucol) =
                        make_float2(gv[j], gv[j + 1]);
                }
            }
        } // sweeps

        // ---- step boundary: write h back into A, load x(t+1) ----
        __syncthreads();   // all A reads of this step complete
#pragma unroll
        for (int j = 0; j < 16; j++) {
            const int mt = j >> 3, nt = (j >> 2) & 1, e = j & 3;
            const int ucol = wn * 16 + nt * 8 + 2 * (lane & 3) + (e & 1);
            const int row  = mt * 16 + (lane >> 2) + ((e >> 1) << 3);
            a_store(sm, row, ucol, gv[j]);
        }
        if (t + 1 < Tt) {
            for (int i = tid; i < BMr * Ff; i += NTm) {
                int r = i / Ff, f = i - r * Ff;
                a_store(sm, r, 256 + f,
                        x[((size_t)(row0 + r) * Tt + (t + 1)) * Ff + f]);
            }
        }
        __syncthreads();
    } // t
}

// ---------------------------------------------------------------------------
// Harness entry point
// ---------------------------------------------------------------------------
extern "C" void kernel_launch(void* const* d_in, const int* in_sizes, int n_in,
                              void* d_out, int out_size) {
    const float* x  = (const float*)d_in[0];  // [B,T,F]
    const float* h0 = (const float*)d_in[1];  // [B,U]
    const float* c0 = (const float*)d_in[2];  // [B,U]
    const float* Wk = (const float*)d_in[3];  // [F,4U]
    const float* Wr = (const float*)d_in[4];  // [U,4U]
    const float* b  = (const float*)d_in[5];  // [4U]
    float* out = (float*)d_out;               // [B,T,U]

    prep_kernel<<<(2 * NCH * 2 * 2048 + 511) / 512, 512>>>(Wr, Wk, b);

    cudaFuncSetAttribute(lstm_hmma,
                         cudaFuncAttributeMaxDynamicSharedMemorySize, SMEM_TOTAL);
    lstm_hmma<<<NCTA, NTm, SMEM_TOTAL>>>(x, h0, c0, out);
}